// round 9
// baseline (speedup 1.0000x reference)
#include <cuda_runtime.h>

// ---------------------------------------------------------------------------
// Masked multi-level MSE loss (B=16, C=256, T=128, S in {80,40,20}):
//   L = mean_l [ sum((M_l * (p_l - t_l))^2) / (C * sum(M_l)) ]
//
// kernel 1 (mask_bits): packs all 3 level masks into 4208 u32 words (16.8KB,
//   4 bits per spatial float4 position) + per-block positive-cell counts.
// kernel 2 (stream): per-thread grid-stride over single f4 units (maximal
//   interleave -> density-balanced), unroll x4 (8 independent LDG.128),
//   nibble mask from the L1-resident bit array (~6 instr/unit), skip at
//   unroll granularity. Last block finalizes into d_out (self-reset ticket).
// ---------------------------------------------------------------------------

#define NB 16
#define NT 128
#define NC 256
#define GRID_BLOCKS 592
#define BT 256
#define TTOT (GRID_BLOCKS * BT)     // 151552

#define MGRID 33
#define MBT 128
#define NWORDS 4208                 // 16*(200+50+13)

__device__ unsigned g_bits[NWORDS];
__device__ int   g_mc[3][MGRID];    // per-mask-block positive-cell counts
__device__ float g_pa[3][GRID_BLOCKS];
__device__ unsigned g_ticket = 0;

// ---------------------------------------------------------------------------
// kernel 1: one thread per 32-bit mask word (8 f4 positions = 32 cells).
__global__ void mask_bits_kernel(const float* __restrict__ bboxes,
                                 const int* __restrict__ batch_idx) {
    __shared__ short4 box[3][NT];   // x=xl, y=xr, z=yt, w=yd (batch-sorted)
    __shared__ int off[NB + 1];
    __shared__ int cnt[NB];

    // counting sort of boxes by batch (3 level-resolutions each)
    if (threadIdx.x < NB) cnt[threadIdx.x] = 0;
    __syncthreads();
    int myb = 0, myrank = 0;
    float4 bb;
    if (threadIdx.x < NT) {
        myb = batch_idx[threadIdx.x];
        bb = ((const float4*)bboxes)[threadIdx.x];
        myrank = atomicAdd(&cnt[myb], 1);
    }
    __syncthreads();
    if (threadIdx.x == 0) {
        int s = 0;
        off[0] = 0;
#pragma unroll
        for (int i = 0; i < NB; i++) { s += cnt[i]; off[i + 1] = s; }
    }
    __syncthreads();
    if (threadIdx.x < NT) {
        const int g = off[myb] + myrank;
#pragma unroll
        for (int lvl = 0; lvl < 3; lvl++) {
            const int S = (lvl == 0) ? 80 : (lvl == 1) ? 40 : 20;
            const float fS = (float)S;
            int xc = (int)floorf(bb.x * fS);
            int yc = (int)floorf(bb.y * fS);
            int w  = (int)floorf(bb.z * fS);
            int h  = (int)floorf(bb.w * fS);
            box[lvl][g] = make_short4((short)max(xc - w / 2, 0),
                                      (short)min(xc + w / 2, S - 1),
                                      (short)max(yc - h / 2, 0),
                                      (short)min(yc + h / 2, S - 1));
        }
    }
    __syncthreads();

    const int w = blockIdx.x * MBT + threadIdx.x;
    int lvl = 0, b = 0, wloc = 0, S = 80;
    const bool valid = (w < NWORDS);
    if (valid) {
        if (w < 3200)      { lvl = 0; b = w / 200;          wloc = w - 200 * b;          S = 80; }
        else if (w < 4000) { lvl = 1; int r = w - 3200; b = r / 50; wloc = r - 50 * b;   S = 40; }
        else               { lvl = 2; int r = w - 4000; b = r / 13; wloc = r - 13 * b;   S = 20; }
    }
    const int S4 = S / 4, CH4 = S * S4;

    unsigned word = 0;
    if (valid) {
        const int j0 = off[b], j1 = off[b + 1];
#pragma unroll 1
        for (int pp = 0; pp < 8; pp++) {
            const int posr = wloc * 8 + pp;
            if (posr >= CH4) break;
            const int y  = posr / S4;
            const int x0 = 4 * (posr - y * S4);
            int nib = 0;
#pragma unroll 1
            for (int j = j0; j < j1; j++) {
                const short4 bx = box[lvl][j];
                if (y >= (int)bx.z && y <= (int)bx.w) {
                    int l = (int)bx.x - x0; l = l < 0 ? 0 : l;
                    int r = (int)bx.y - x0; r = r > 3 ? 3 : r;
                    if (l <= r) nib |= (0xF << l) & (0xF >> (3 - r));
                }
            }
            word |= (unsigned)nib << (pp * 4);
        }
        g_bits[w] = word;
    }

    // per-level positive-cell counts (block partials, no atomics)
    int pc = __popc(word);
    int c0 = (valid && lvl == 0) ? pc : 0;
    int c1 = (valid && lvl == 1) ? pc : 0;
    int c2 = (valid && lvl == 2) ? pc : 0;
    __shared__ int sm0[4], sm1[4], sm2[4];
#pragma unroll
    for (int o = 16; o; o >>= 1) {
        c0 += __shfl_down_sync(0xffffffffu, c0, o);
        c1 += __shfl_down_sync(0xffffffffu, c1, o);
        c2 += __shfl_down_sync(0xffffffffu, c2, o);
    }
    const int lane = threadIdx.x & 31, warp = threadIdx.x >> 5;
    if (lane == 0) { sm0[warp] = c0; sm1[warp] = c1; sm2[warp] = c2; }
    __syncthreads();
    if (threadIdx.x == 0) {
        int s0 = 0, s1 = 0, s2 = 0;
#pragma unroll
        for (int i = 0; i < MBT / 32; i++) { s0 += sm0[i]; s1 += sm1[i]; s2 += sm2[i]; }
        g_mc[0][blockIdx.x] = s0;
        g_mc[1][blockIdx.x] = s1;
        g_mc[2][blockIdx.x] = s2;
    }
}

// ---------------------------------------------------------------------------
__device__ __forceinline__ float block_sum_f(float v, float* sm) {
#pragma unroll
    for (int o = 16; o; o >>= 1) v += __shfl_down_sync(0xffffffffu, v, o);
    const int lane = threadIdx.x & 31, warp = threadIdx.x >> 5;
    if (lane == 0) sm[warp] = v;
    __syncthreads();
    v = (threadIdx.x < (BT / 32)) ? sm[threadIdx.x] : 0.f;
    if (warp == 0) {
#pragma unroll
        for (int o = 16; o; o >>= 1) v += __shfl_down_sync(0xffffffffu, v, o);
    }
    __syncthreads();
    return v;
}

// ---------------------------------------------------------------------------
template <int S>
__device__ __forceinline__ unsigned get_nib(unsigned u, unsigned lvloff,
                                            unsigned W) {
    constexpr unsigned CH4 = (unsigned)S * (S / 4);
    const unsigned b    = u / ((unsigned)NC * CH4);
    const unsigned posr = u % CH4;
    const unsigned word = __ldg(&g_bits[lvloff + b * W + (posr >> 3)]);
    return (word >> ((posr & 7u) * 4u)) & 0xFu;
}

__device__ __forceinline__ void unit_fp(const float4* __restrict__ p,
                                        const float4* __restrict__ q,
                                        unsigned u, unsigned nib,
                                        float& acc0, float& acc1) {
    const float fm0 = __uint_as_float(( nib       & 1u) * 0x3F800000u);
    const float fm1 = __uint_as_float(((nib >> 1) & 1u) * 0x3F800000u);
    const float fm2 = __uint_as_float(((nib >> 2) & 1u) * 0x3F800000u);
    const float fm3 = __uint_as_float(((nib >> 3) & 1u) * 0x3F800000u);
    const float4 a = __ldg(p + u);
    const float4 c = __ldg(q + u);
    float d, e;
    d = a.x - c.x; e = fm0 * d; acc0 = fmaf(e, d, acc0);
    d = a.y - c.y; e = fm1 * d; acc1 = fmaf(e, d, acc1);
    d = a.z - c.z; e = fm2 * d; acc0 = fmaf(e, d, acc0);
    d = a.w - c.w; e = fm3 * d; acc1 = fmaf(e, d, acc1);
}

// Stream one level: grid-stride over single f4 units, unroll x UNROLL.
template <int S, int UNROLL>
__device__ __forceinline__ float level_sum(const float4* __restrict__ p,
                                           const float4* __restrict__ q,
                                           unsigned lvloff, unsigned W,
                                           unsigned gid) {
    constexpr unsigned CH4 = (unsigned)S * (S / 4);
    constexpr unsigned N4  = (unsigned)NB * NC * CH4;
    constexpr unsigned T   = (unsigned)TTOT;

    float acc0 = 0.f, acc1 = 0.f;
    unsigned i = gid;

    if constexpr (UNROLL == 4) {
#pragma unroll 1
        for (; i + 3u * T < N4; i += 4u * T) {
            const unsigned n0 = get_nib<S>(i,          lvloff, W);
            const unsigned n1 = get_nib<S>(i + T,      lvloff, W);
            const unsigned n2 = get_nib<S>(i + 2u * T, lvloff, W);
            const unsigned n3 = get_nib<S>(i + 3u * T, lvloff, W);
            if ((n0 | n1 | n2 | n3) == 0u) continue;
            unit_fp(p, q, i,          n0, acc0, acc1);
            unit_fp(p, q, i + T,      n1, acc0, acc1);
            unit_fp(p, q, i + 2u * T, n2, acc0, acc1);
            unit_fp(p, q, i + 3u * T, n3, acc0, acc1);
        }
    } else if constexpr (UNROLL == 2) {
#pragma unroll 1
        for (; i + T < N4; i += 2u * T) {
            const unsigned n0 = get_nib<S>(i,     lvloff, W);
            const unsigned n1 = get_nib<S>(i + T, lvloff, W);
            if ((n0 | n1) == 0u) continue;
            unit_fp(p, q, i,     n0, acc0, acc1);
            unit_fp(p, q, i + T, n1, acc0, acc1);
        }
    }
#pragma unroll 1
    for (; i < N4; i += T) {
        const unsigned n0 = get_nib<S>(i, lvloff, W);
        if (n0 == 0u) continue;
        unit_fp(p, q, i, n0, acc0, acc1);
    }
    return acc0 + acc1;
}

// ---------------------------------------------------------------------------
__global__ void __launch_bounds__(BT, 4)
stream_kernel(const float4* __restrict__ p0, const float4* __restrict__ t0,
              const float4* __restrict__ p1, const float4* __restrict__ t1,
              const float4* __restrict__ p2, const float4* __restrict__ t2,
              float* __restrict__ out) {
    const unsigned gid = blockIdx.x * BT + threadIdx.x;

    float a0 = level_sum<80, 4>(p0, t0, 0u,    200u, gid);
    float a1 = level_sum<40, 2>(p1, t1, 3200u, 50u,  gid);
    float a2 = level_sum<20, 1>(p2, t2, 4000u, 13u,  gid);

    __shared__ float smf[32];
    a0 = block_sum_f(a0, smf);
    a1 = block_sum_f(a1, smf);
    a2 = block_sum_f(a2, smf);

    __shared__ bool s_last;
    if (threadIdx.x == 0) {
        g_pa[0][blockIdx.x] = a0;
        g_pa[1][blockIdx.x] = a1;
        g_pa[2][blockIdx.x] = a2;
        __threadfence();
        unsigned n = atomicAdd(&g_ticket, 1u);
        s_last = (n == GRID_BLOCKS - 1);
    }
    __syncthreads();
    if (!s_last) return;

    // ---- finalize (last block only) ----
    float fa0 = 0.f, fa1 = 0.f, fa2 = 0.f;
    for (int i = threadIdx.x; i < GRID_BLOCKS; i += BT) {
        fa0 += g_pa[0][i]; fa1 += g_pa[1][i]; fa2 += g_pa[2][i];
    }
    fa0 = block_sum_f(fa0, smf);
    fa1 = block_sum_f(fa1, smf);
    fa2 = block_sum_f(fa2, smf);

    if (threadIdx.x == 0) {
        int fc0 = 0, fc1 = 0, fc2 = 0;
        for (int i = 0; i < MGRID; i++) {
            fc0 += g_mc[0][i]; fc1 += g_mc[1][i]; fc2 += g_mc[2][i];
        }
        double L = (double)fa0 / (256.0 * (double)fc0) +
                   (double)fa1 / (256.0 * (double)fc1) +
                   (double)fa2 / (256.0 * (double)fc2);
        out[0] = (float)(L / 3.0);
        __threadfence();
        g_ticket = 0;   // restore for next graph replay
    }
}

// ---------------------------------------------------------------------------
extern "C" void kernel_launch(void* const* d_in, const int* in_sizes, int n_in,
                              void* d_out, int out_size) {
    // input order: pred0, true0, pred1, true1, pred2, true2, bboxes, batch_idx, cls
    const float4* p0 = (const float4*)d_in[0];
    const float4* t0 = (const float4*)d_in[1];
    const float4* p1 = (const float4*)d_in[2];
    const float4* t1 = (const float4*)d_in[3];
    const float4* p2 = (const float4*)d_in[4];
    const float4* t2 = (const float4*)d_in[5];
    const float* bboxes = (const float*)d_in[6];
    const int* batch_idx = (const int*)d_in[7];

    mask_bits_kernel<<<MGRID, MBT>>>(bboxes, batch_idx);
    stream_kernel<<<GRID_BLOCKS, BT>>>(p0, t0, p1, t1, p2, t2, (float*)d_out);
}